// round 14
// baseline (speedup 1.0000x reference)
#include <cuda_runtime.h>
#include <cuda_bf16.h>
#include <cstdint>

#define TD 768
#define NHEADS 12
#define HDIM 64
#define NSEQ 2048
#define NROWS 4096
#define NBH 24
#define ATT_SCALE 0.125f
#define LN_EPS 1e-5f
#define LOG2E 1.4426950408889634f

typedef __nv_bfloat16 bf16;

__device__ bf16 g_h[(size_t)NROWS * TD];
__device__ bf16 g_wt[4][(size_t)TD * TD];            // W^T [n][k]
__device__ bf16 g_q[(size_t)NBH * NSEQ * HDIM];      // pre-scaled by log2(e)
__device__ bf16 g_k[(size_t)NBH * NSEQ * HDIM];
__device__ bf16 g_vt[(size_t)NBH * HDIM * NSEQ];     // V^T [bh][d][seq]
__device__ bf16 g_vals[(size_t)NROWS * TD];

// ---------------- helpers ----------------
__device__ __forceinline__ uint32_t smem_u32(const void* p) {
    uint32_t a;
    asm("{ .reg .u64 t; cvta.to.shared.u64 t, %1; cvt.u32.u64 %0, t; }" : "=r"(a) : "l"(p));
    return a;
}
__device__ __forceinline__ uint32_t row128(int r, int cb) {
    uint32_t o = (uint32_t)(r * 128 + cb);
    return o ^ ((o >> 3) & 0x70);
}
__device__ __forceinline__ uint32_t pk2(float a, float b) {
    uint32_t r;
    asm("cvt.rn.satfinite.bf16x2.f32 %0, %1, %2;" : "=r"(r) : "f"(b), "f"(a));
    return r;
}
__device__ __forceinline__ float ex2(float x) {
    float r;
    asm("ex2.approx.ftz.f32 %0, %1;" : "=f"(r) : "f"(x));
    return r;
}
__device__ __forceinline__ void ldsm4(uint32_t& r0, uint32_t& r1, uint32_t& r2, uint32_t& r3,
                                      uint32_t addr) {
    asm volatile("ldmatrix.sync.aligned.m8n8.x4.shared.b16 {%0,%1,%2,%3}, [%4];"
        : "=r"(r0), "=r"(r1), "=r"(r2), "=r"(r3) : "r"(addr));
}
__device__ __forceinline__ void mma16816(float* c, const uint32_t* a, const uint32_t* b) {
    asm volatile("mma.sync.aligned.m16n8k16.row.col.f32.bf16.bf16.f32 "
        "{%0,%1,%2,%3}, {%4,%5,%6,%7}, {%8,%9}, {%0,%1,%2,%3};"
        : "+f"(c[0]), "+f"(c[1]), "+f"(c[2]), "+f"(c[3])
        : "r"(a[0]), "r"(a[1]), "r"(a[2]), "r"(a[3]), "r"(b[0]), "r"(b[1]));
}
#define CP16(dst, src) asm volatile("cp.async.cg.shared.global [%0], [%1], 16;" :: "r"(dst), "l"(src))
#define CP_COMMIT()    asm volatile("cp.async.commit_group;")
#define CP_WAIT0()     asm volatile("cp.async.wait_group 0;")
#define CP_WAIT1()     asm volatile("cp.async.wait_group 1;")

// ---------------- LayerNorm -> bf16 ----------------
__global__ __launch_bounds__(256) void ln_kernel(const float* __restrict__ x,
                                                 const float* __restrict__ gamma,
                                                 const float* __restrict__ beta) {
    int row = blockIdx.x;
    const float* xr = x + (size_t)row * TD;
    float v[3], sum = 0.f, sq = 0.f;
#pragma unroll
    for (int p = 0; p < 3; p++) {
        v[p] = xr[threadIdx.x + p * 256];
        sum += v[p]; sq += v[p] * v[p];
    }
#pragma unroll
    for (int o = 16; o; o >>= 1) {
        sum += __shfl_xor_sync(~0u, sum, o);
        sq  += __shfl_xor_sync(~0u, sq, o);
    }
    __shared__ float ss[8], sv[8];
    int w = threadIdx.x >> 5, l = threadIdx.x & 31;
    if (l == 0) { ss[w] = sum; sv[w] = sq; }
    __syncthreads();
    if (w == 0) {
        sum = ss[l & 7]; sq = sv[l & 7];
#pragma unroll
        for (int o = 4; o; o >>= 1) {
            sum += __shfl_xor_sync(~0u, sum, o);
            sq  += __shfl_xor_sync(~0u, sq, o);
        }
        if (l == 0) { ss[0] = sum; sv[0] = sq; }
    }
    __syncthreads();
    float mean = ss[0] * (1.f / TD);
    float rstd = rsqrtf(sv[0] * (1.f / TD) - mean * mean + LN_EPS);
#pragma unroll
    for (int p = 0; p < 3; p++) {
        int i = threadIdx.x + p * 256;
        g_h[(size_t)row * TD + i] =
            __float2bfloat16_rn((v[p] - mean) * rstd * gamma[i] + beta[i]);
    }
}

// ---------------- Weight transpose: wt[n][k] = W[k][n] (bf16) ----------------
__global__ __launch_bounds__(256) void wtrans_kernel(const float* __restrict__ Wq,
                                                     const float* __restrict__ Wk,
                                                     const float* __restrict__ Wv,
                                                     const float* __restrict__ Wo) {
    int z = blockIdx.z;
    const float* W = (z == 0) ? Wq : (z == 1) ? Wk : (z == 2) ? Wv : Wo;
    __shared__ float t[32][33];
    int n0 = blockIdx.x * 32, k0 = blockIdx.y * 32;
    int tx = threadIdx.x, ty = threadIdx.y;
#pragma unroll
    for (int i = 0; i < 4; i++)
        t[ty + 8 * i][tx] = W[(size_t)(k0 + ty + 8 * i) * TD + n0 + tx];
    __syncthreads();
#pragma unroll
    for (int i = 0; i < 4; i++)
        g_wt[z][(size_t)(n0 + ty + 8 * i) * TD + k0 + tx] =
            __float2bfloat16_rn(t[tx][ty + 8 * i]);
}

// ---------------- core 128x128 GEMM mainloop (3-stage cp.async, 1 sync/iter)
// smem: stage s at s*32768 { A 16K, B 16K }; 96KB total. 256 threads, 8 warps.
__device__ __forceinline__ void gemm128(const bf16* __restrict__ A, const bf16* __restrict__ Bt,
                                        char* smem, float c[4][4][4], int m0, int n0) {
    int tid = threadIdx.x, warp = tid >> 5, lane = tid & 31;
    int wm = (warp >> 2) * 64, wn = (warp & 3) * 32;
    uint32_t sb = smem_u32(smem);
    int arow = wm + (lane & 15);
    int acolx = (lane & 16) ? 16 : 0;
    int brow0 = wn + ((lane & 16) ? 8 : 0) + (lane & 7);
    int bcolx = (lane & 8) ? 16 : 0;

    int lr = tid >> 3, lch = tid & 7;
    uint32_t lsw[4];
#pragma unroll
    for (int p = 0; p < 4; p++) lsw[p] = row128(lr + p * 32, lch * 16);

    // prologue: stages 0, 1
#pragma unroll
    for (int s = 0; s < 2; s++) {
        uint32_t st = (uint32_t)s * 32768;
#pragma unroll
        for (int p = 0; p < 4; p++) {
            int r = lr + p * 32;
            CP16(sb + st + lsw[p],         A  + (size_t)(m0 + r) * TD + s * 64 + lch * 8);
            CP16(sb + st + 16384 + lsw[p], Bt + (size_t)(n0 + r) * TD + s * 64 + lch * 8);
        }
        CP_COMMIT();
    }

    int stg = 0;
    for (int i = 0; i < 12; i++) {
        if (i < 11) { CP_WAIT1(); } else { CP_WAIT0(); }
        __syncthreads();   // all warps done computing stage (i-1); safe to overwrite
        if (i < 10) {
            int s2 = stg + 2; if (s2 >= 3) s2 -= 3;
            uint32_t st = (uint32_t)s2 * 32768;
#pragma unroll
            for (int p = 0; p < 4; p++) {
                int r = lr + p * 32;
                CP16(sb + st + lsw[p],         A  + (size_t)(m0 + r) * TD + (i + 2) * 64 + lch * 8);
                CP16(sb + st + 16384 + lsw[p], Bt + (size_t)(n0 + r) * TD + (i + 2) * 64 + lch * 8);
            }
            CP_COMMIT();
        }
        uint32_t sbase = sb + (uint32_t)stg * 32768;
#pragma unroll
        for (int ks = 0; ks < 4; ks++) {
            uint32_t af[4][4], bfr[4][2];
#pragma unroll
            for (int mf = 0; mf < 4; mf++)
                ldsm4(af[mf][0], af[mf][1], af[mf][2], af[mf][3],
                      sbase + row128(arow + mf * 16, ks * 32 + acolx));
#pragma unroll
            for (int j = 0; j < 4; j += 2)
                ldsm4(bfr[j][0], bfr[j][1], bfr[j + 1][0], bfr[j + 1][1],
                      sbase + 16384 + row128(brow0 + j * 8, ks * 32 + bcolx));
#pragma unroll
            for (int mf = 0; mf < 4; mf++)
#pragma unroll
                for (int nf = 0; nf < 4; nf++)
                    mma16816(c[mf][nf], af[mf], bfr[nf]);
        }
        stg = stg + 1; if (stg >= 3) stg = 0;
    }
    __syncthreads();   // epilogue may reuse smem
}

// ---------------- QKV GEMM (Q scaled by log2e; V written transposed) --------
#define GEMM_SMEM 98304
__global__ __launch_bounds__(256) void qkv_kernel() {
    extern __shared__ char smem[];
    int z = blockIdx.z;
    int m0 = blockIdx.x * 128, n0 = blockIdx.y * 128;
    float c[4][4][4] = {};
    gemm128(g_h, g_wt[z], smem, c, m0, n0);

    int tid = threadIdx.x, warp = tid >> 5, lane = tid & 31;
    int wm = (warp >> 2) * 64, wn = (warp & 3) * 32;

    if (z < 2) {
        bf16* G = (z == 0) ? g_q : g_k;
        float sc = (z == 0) ? LOG2E : 1.0f;
#pragma unroll
        for (int mf = 0; mf < 4; mf++) {
            int row = m0 + wm + mf * 16 + (lane >> 2);
            int batch = row >> 11, seq = row & (NSEQ - 1);
#pragma unroll
            for (int nf = 0; nf < 4; nf++) {
                int col = n0 + wn + nf * 8 + 2 * (lane & 3);
                int head = col >> 6, d = col & 63;
                bf16* D = G + ((size_t)(batch * NHEADS + head) * NSEQ + seq) * HDIM + d;
                *(uint32_t*)D = pk2(c[mf][nf][0] * sc, c[mf][nf][1] * sc);
                *(uint32_t*)(D + 8 * HDIM) = pk2(c[mf][nf][2] * sc, c[mf][nf][3] * sc);
            }
        }
    } else {
        bf16* ts = (bf16*)smem;     // [128 cols n][136 pitch m]
#pragma unroll
        for (int mf = 0; mf < 4; mf++) {
            int lr0 = wm + mf * 16 + (lane >> 2);
#pragma unroll
            for (int nf = 0; nf < 4; nf++) {
                int lc = wn + nf * 8 + 2 * (lane & 3);
                uint32_t lo = pk2(c[mf][nf][0], c[mf][nf][2]);
                uint32_t hi = pk2(c[mf][nf][1], c[mf][nf][3]);
                ts[(size_t)lc * 136 + lr0]           = __ushort_as_bfloat16((unsigned short)(lo & 0xffff));
                ts[(size_t)lc * 136 + lr0 + 8]       = __ushort_as_bfloat16((unsigned short)(lo >> 16));
                ts[(size_t)(lc + 1) * 136 + lr0]     = __ushort_as_bfloat16((unsigned short)(hi & 0xffff));
                ts[(size_t)(lc + 1) * 136 + lr0 + 8] = __ushort_as_bfloat16((unsigned short)(hi >> 16));
            }
        }
        __syncthreads();
        int n = tid >> 1, mh = (tid & 1) * 64;
        int col = n0 + n, head = col >> 6, d = col & 63;
        int batch = blockIdx.x >> 4;
        int seq0 = (m0 & (NSEQ - 1)) + mh;
        bf16* D = g_vt + ((size_t)(batch * NHEADS + head) * HDIM + d) * NSEQ + seq0;
#pragma unroll
        for (int s = 0; s < 8; s++)
            *(uint4*)(D + s * 8) = *(uint4*)&ts[(size_t)n * 136 + mh + s * 8];
    }
}

// ---------------- Attention: 128 q/CTA, 4 warps x 32 q rows (R11 version) ---
// smem: Q 16K @0 | K 2x8K @16384 | V^T 2x8K @32768  (48KB static)
__global__ __launch_bounds__(128, 2) void attn_kernel() {
    __shared__ char smem[49152];
    int tid = threadIdx.x, warp = tid >> 5, lane = tid & 31;
    int q0 = blockIdx.x * 128, bh = blockIdx.y;

    const bf16* Qg = g_q + (size_t)bh * NSEQ * HDIM;
    const bf16* Kg = g_k + (size_t)bh * NSEQ * HDIM;
    const bf16* Vt = g_vt + (size_t)bh * HDIM * NSEQ;
    uint32_t sb = smem_u32(smem);

#pragma unroll
    for (int p = 0; p < 8; p++) {
        int idx = tid + p * 128;
        int r = idx >> 3, ch = idx & 7;
        CP16(sb + row128(r, ch * 16), Qg + (size_t)(q0 + r) * HDIM + ch * 8);
    }
    CP_COMMIT();

#pragma unroll
    for (int p = 0; p < 4; p++) {
        int idx = tid + p * 128;
        int r = idx >> 3, ch = idx & 7;
        uint32_t sw = row128(r, ch * 16);
        CP16(sb + 16384 + sw, Kg + (size_t)r * HDIM + ch * 8);
        CP16(sb + 32768 + sw, Vt + (size_t)r * NSEQ + ch * 8);
    }
    CP_COMMIT();

    CP_WAIT1();
    __syncthreads();

    uint32_t qf[2][4][4];
    int arow = warp * 32 + (lane & 15);
    int acolx = (lane & 16) ? 16 : 0;
#pragma unroll
    for (int mf = 0; mf < 2; mf++)
#pragma unroll
        for (int ks = 0; ks < 4; ks++)
            ldsm4(qf[mf][ks][0], qf[mf][ks][1], qf[mf][ks][2], qf[mf][ks][3],
                  sb + row128(arow + mf * 16, ks * 32 + acolx));

    float of[2][8][4] = {};
    float lsum[2][2] = {};
    int brow0 = ((lane & 16) ? 8 : 0) + (lane & 7);
    int bcolx = (lane & 8) ? 16 : 0;

    for (int kt = 0; kt < NSEQ / 64; kt++) {
        uint32_t stg = (uint32_t)(kt & 1) * 8192;
        if (kt < NSEQ / 64 - 1) {
            uint32_t nst = (uint32_t)((kt + 1) & 1) * 8192;
#pragma unroll
            for (int p = 0; p < 4; p++) {
                int idx = tid + p * 128;
                int r = idx >> 3, ch = idx & 7;
                uint32_t sw = row128(r, ch * 16);
                CP16(sb + 16384 + nst + sw, Kg + (size_t)((kt + 1) * 64 + r) * HDIM + ch * 8);
                CP16(sb + 32768 + nst + sw, Vt + (size_t)r * NSEQ + (kt + 1) * 64 + ch * 8);
            }
            CP_COMMIT();
            CP_WAIT1();
        } else {
            CP_WAIT0();
        }
        __syncthreads();

        // S' = (log2e*Q) @ K^T in two 32-kv halves; P = exp2(S')
        uint32_t pf[2][4][4];
#pragma unroll
        for (int half = 0; half < 2; half++) {
            float sf[2][4][4] = {};
#pragma unroll
            for (int ks = 0; ks < 4; ks++) {
                uint32_t bfr[4][2];
#pragma unroll
                for (int j = 0; j < 4; j += 2)
                    ldsm4(bfr[j][0], bfr[j][1], bfr[j + 1][0], bfr[j + 1][1],
                          sb + 16384 + stg + row128(brow0 + half * 32 + j * 8, ks * 32 + bcolx));
#pragma unroll
                for (int mf = 0; mf < 2; mf++)
#pragma unroll
                    for (int nf = 0; nf < 4; nf++)
                        mma16816(sf[mf][nf], qf[mf][ks], bfr[nf]);
            }
#pragma unroll
            for (int mf = 0; mf < 2; mf++)
#pragma unroll
                for (int j = 0; j < 2; j++) {
                    float e00 = ex2(sf[mf][2 * j][0]),     e01 = ex2(sf[mf][2 * j][1]);
                    float e02 = ex2(sf[mf][2 * j][2]),     e03 = ex2(sf[mf][2 * j][3]);
                    float e10 = ex2(sf[mf][2 * j + 1][0]), e11 = ex2(sf[mf][2 * j + 1][1]);
                    float e12 = ex2(sf[mf][2 * j + 1][2]), e13 = ex2(sf[mf][2 * j + 1][3]);
                    int pj = half * 2 + j;
                    pf[mf][pj][0] = pk2(e00, e01);
                    pf[mf][pj][1] = pk2(e02, e03);
                    pf[mf][pj][2] = pk2(e10, e11);
                    pf[mf][pj][3] = pk2(e12, e13);
                    lsum[mf][0] += e00 + e01 + e10 + e11;
                    lsum[mf][1] += e02 + e03 + e12 + e13;
                }
        }

        // O += P @ V : B from V^T [d][kv]
#pragma unroll
        for (int ks = 0; ks < 4; ks++) {
            uint32_t bfr[8][2];
#pragma unroll
            for (int j = 0; j < 8; j += 2)
                ldsm4(bfr[j][0], bfr[j][1], bfr[j + 1][0], bfr[j + 1][1],
                      sb + 32768 + stg + row128(brow0 + j * 8, ks * 32 + bcolx));
#pragma unroll
            for (int mf = 0; mf < 2; mf++)
#pragma unroll
                for (int nf = 0; nf < 8; nf++)
                    mma16816(of[mf][nf], pf[mf][ks], bfr[nf]);
        }
        __syncthreads();
    }

    float scale[2][2];
#pragma unroll
    for (int mf = 0; mf < 2; mf++)
#pragma unroll
        for (int h = 0; h < 2; h++) {
            float l = lsum[mf][h];
            l += __shfl_xor_sync(~0u, l, 1);
            l += __shfl_xor_sync(~0u, l, 2);
            scale[mf][h] = ATT_SCALE / l;
        }
    int batch = bh / NHEADS, head = bh % NHEADS;
#pragma unroll
    for (int mf = 0; mf < 2; mf++) {
        int r0 = q0 + warp * 32 + mf * 16 + (lane >> 2);
#pragma unroll
        for (int nf = 0; nf < 8; nf++) {
            int d = nf * 8 + 2 * (lane & 3);
            bf16* D = g_vals + ((size_t)(batch * NSEQ + r0)) * TD + head * HDIM + d;
            *(uint32_t*)D = pk2(of[mf][nf][0] * scale[mf][0], of[mf][nf][1] * scale[mf][0]);
            *(uint32_t*)(D + (size_t)8 * TD) =
                pk2(of[mf][nf][2] * scale[mf][1], of[mf][nf][3] * scale[mf][1]);
        }
    }
}

// ---------------- Output projection: out = vals @ Wo + bo + x ----------------
__global__ __launch_bounds__(256) void out_kernel(const float* __restrict__ bo,
                                                  const float* __restrict__ x,
                                                  float* __restrict__ out) {
    extern __shared__ char smem[];
    int m0 = blockIdx.x * 128, n0 = blockIdx.y * 128;
    float c[4][4][4] = {};
    gemm128(g_vals, g_wt[3], smem, c, m0, n0);

    int tid = threadIdx.x, warp = tid >> 5, lane = tid & 31;
    int wm = (warp >> 2) * 64, wn = (warp & 3) * 32;
#pragma unroll
    for (int mf = 0; mf < 4; mf++) {
        int row = m0 + wm + mf * 16 + (lane >> 2);
#pragma unroll
        for (int nf = 0; nf < 4; nf++) {
            int col = n0 + wn + nf * 8 + 2 * (lane & 3);
            float2 bv = *(const float2*)(bo + col);
            size_t off0 = (size_t)row * TD + col;
            size_t off1 = (size_t)(row + 8) * TD + col;
            float2 x0 = *(const float2*)(x + off0);
            float2 x1 = *(const float2*)(x + off1);
            *(float2*)(out + off0) = make_float2(c[mf][nf][0] + bv.x + x0.x,
                                                 c[mf][nf][1] + bv.y + x0.y);
            *(float2*)(out + off1) = make_float2(c[mf][nf][2] + bv.x + x1.x,
                                                 c[mf][nf][3] + bv.y + x1.y);
        }
    }
}

// ---------------------------------------------------------------------------
extern "C" void kernel_launch(void* const* d_in, const int* in_sizes, int n_in,
                              void* d_out, int out_size) {
    (void)in_sizes; (void)n_in; (void)out_size;
    const float* x     = (const float*)d_in[0];
    const float* Wq    = (const float*)d_in[1];
    const float* Wk    = (const float*)d_in[2];
    const float* Wv    = (const float*)d_in[3];
    const float* Wo    = (const float*)d_in[4];
    const float* bo    = (const float*)d_in[5];
    const float* gamma = (const float*)d_in[6];
    const float* beta  = (const float*)d_in[7];
    float* out = (float*)d_out;

    cudaFuncSetAttribute(qkv_kernel, cudaFuncAttributeMaxDynamicSharedMemorySize, GEMM_SMEM);
    cudaFuncSetAttribute(out_kernel, cudaFuncAttributeMaxDynamicSharedMemorySize, GEMM_SMEM);

    ln_kernel<<<NROWS, 256>>>(x, gamma, beta);
    wtrans_kernel<<<dim3(TD / 32, TD / 32, 4), dim3(32, 8)>>>(Wq, Wk, Wv, Wo);
    qkv_kernel<<<dim3(NROWS / 128, TD / 128, 3), 256, GEMM_SMEM>>>();
    attn_kernel<<<dim3(NSEQ / 128, NBH), 128>>>();
    out_kernel<<<dim3(NROWS / 128, TD / 128), 256, GEMM_SMEM>>>(bo, x, out);
}

// round 15
// speedup vs baseline: 1.0747x; 1.0747x over previous
#include <cuda_runtime.h>
#include <cuda_bf16.h>
#include <cstdint>

#define TD 768
#define NHEADS 12
#define HDIM 64
#define NSEQ 2048
#define NROWS 4096
#define NBH 24
#define ATT_SCALE 0.125f
#define LN_EPS 1e-5f
#define LOG2E 1.4426950408889634f

typedef __nv_bfloat16 bf16;

__device__ bf16 g_h[(size_t)NROWS * TD];
__device__ bf16 g_wt[4][(size_t)TD * TD];            // W^T [n][k]
__device__ bf16 g_q[(size_t)NBH * NSEQ * HDIM];      // pre-scaled by log2(e)
__device__ bf16 g_k[(size_t)NBH * NSEQ * HDIM];
__device__ bf16 g_vt[(size_t)NBH * HDIM * NSEQ];     // V^T [bh][d][seq]
__device__ bf16 g_vals[(size_t)NROWS * TD];

// ---------------- helpers ----------------
__device__ __forceinline__ uint32_t smem_u32(const void* p) {
    uint32_t a;
    asm("{ .reg .u64 t; cvta.to.shared.u64 t, %1; cvt.u32.u64 %0, t; }" : "=r"(a) : "l"(p));
    return a;
}
__device__ __forceinline__ uint32_t row128(int r, int cb) {
    uint32_t o = (uint32_t)(r * 128 + cb);
    return o ^ ((o >> 3) & 0x70);
}
__device__ __forceinline__ uint32_t pk2(float a, float b) {
    uint32_t r;
    asm("cvt.rn.satfinite.bf16x2.f32 %0, %1, %2;" : "=r"(r) : "f"(b), "f"(a));
    return r;
}
__device__ __forceinline__ float ex2(float x) {
    float r;
    asm("ex2.approx.ftz.f32 %0, %1;" : "=f"(r) : "f"(x));
    return r;
}
__device__ __forceinline__ void ldsm4(uint32_t& r0, uint32_t& r1, uint32_t& r2, uint32_t& r3,
                                      uint32_t addr) {
    asm volatile("ldmatrix.sync.aligned.m8n8.x4.shared.b16 {%0,%1,%2,%3}, [%4];"
        : "=r"(r0), "=r"(r1), "=r"(r2), "=r"(r3) : "r"(addr));
}
__device__ __forceinline__ void mma16816(float* c, const uint32_t* a, const uint32_t* b) {
    asm volatile("mma.sync.aligned.m16n8k16.row.col.f32.bf16.bf16.f32 "
        "{%0,%1,%2,%3}, {%4,%5,%6,%7}, {%8,%9}, {%0,%1,%2,%3};"
        : "+f"(c[0]), "+f"(c[1]), "+f"(c[2]), "+f"(c[3])
        : "r"(a[0]), "r"(a[1]), "r"(a[2]), "r"(a[3]), "r"(b[0]), "r"(b[1]));
}
#define CP16(dst, src) asm volatile("cp.async.cg.shared.global [%0], [%1], 16;" :: "r"(dst), "l"(src))
#define CP_COMMIT()    asm volatile("cp.async.commit_group;")
#define CP_WAIT0()     asm volatile("cp.async.wait_group 0;")
#define CP_WAIT1()     asm volatile("cp.async.wait_group 1;")

// ---------------- Fused prep: LN (blocks 0..4095) + W transpose (rest) ------
// ln: one block per row. wtrans: 32x32 tile per block, flat 256 threads.
__global__ __launch_bounds__(256) void prep_kernel(const float* __restrict__ x,
                                                   const float* __restrict__ gamma,
                                                   const float* __restrict__ beta,
                                                   const float* __restrict__ Wq,
                                                   const float* __restrict__ Wk,
                                                   const float* __restrict__ Wv,
                                                   const float* __restrict__ Wo) {
    __shared__ float ss[8], sv[8];
    __shared__ float t[32][33];
    int bx = blockIdx.x;
    if (bx < NROWS) {
        int row = bx;
        const float* xr = x + (size_t)row * TD;
        float v[3], sum = 0.f, sq = 0.f;
#pragma unroll
        for (int p = 0; p < 3; p++) {
            v[p] = xr[threadIdx.x + p * 256];
            sum += v[p]; sq += v[p] * v[p];
        }
#pragma unroll
        for (int o = 16; o; o >>= 1) {
            sum += __shfl_xor_sync(~0u, sum, o);
            sq  += __shfl_xor_sync(~0u, sq, o);
        }
        int w = threadIdx.x >> 5, l = threadIdx.x & 31;
        if (l == 0) { ss[w] = sum; sv[w] = sq; }
        __syncthreads();
        if (w == 0) {
            sum = ss[l & 7]; sq = sv[l & 7];
#pragma unroll
            for (int o = 4; o; o >>= 1) {
                sum += __shfl_xor_sync(~0u, sum, o);
                sq  += __shfl_xor_sync(~0u, sq, o);
            }
            if (l == 0) { ss[0] = sum; sv[0] = sq; }
        }
        __syncthreads();
        float mean = ss[0] * (1.f / TD);
        float rstd = rsqrtf(sv[0] * (1.f / TD) - mean * mean + LN_EPS);
#pragma unroll
        for (int p = 0; p < 3; p++) {
            int i = threadIdx.x + p * 256;
            g_h[(size_t)row * TD + i] =
                __float2bfloat16_rn((v[p] - mean) * rstd * gamma[i] + beta[i]);
        }
    } else {
        int tile = bx - NROWS;                 // 0 .. 4*24*24-1
        int z = tile / 576;
        int rem = tile - z * 576;
        int n0 = (rem % 24) * 32, k0 = (rem / 24) * 32;
        const float* W = (z == 0) ? Wq : (z == 1) ? Wk : (z == 2) ? Wv : Wo;
        int tx = threadIdx.x & 31, ty = threadIdx.x >> 5;
#pragma unroll
        for (int i = 0; i < 4; i++)
            t[ty + 8 * i][tx] = W[(size_t)(k0 + ty + 8 * i) * TD + n0 + tx];
        __syncthreads();
#pragma unroll
        for (int i = 0; i < 4; i++)
            g_wt[z][(size_t)(n0 + ty + 8 * i) * TD + k0 + tx] =
                __float2bfloat16_rn(t[tx][ty + 8 * i]);
    }
}

// ---------------- core 128x128 GEMM mainloop (2-stage cp.async, R11) --------
__device__ __forceinline__ void gemm128(const bf16* __restrict__ A, const bf16* __restrict__ Bt,
                                        char* smem, float c[4][4][4], int m0, int n0) {
    int tid = threadIdx.x, warp = tid >> 5, lane = tid & 31;
    int wm = (warp >> 2) * 64, wn = (warp & 3) * 32;
    uint32_t sb = smem_u32(smem);
    int arow = wm + (lane & 15);
    int acolx = (lane & 16) ? 16 : 0;
    int brow0 = wn + ((lane & 16) ? 8 : 0) + (lane & 7);
    int bcolx = (lane & 8) ? 16 : 0;

    int lr = tid >> 3, lch = tid & 7;
    uint32_t lsw[4];
#pragma unroll
    for (int p = 0; p < 4; p++) lsw[p] = row128(lr + p * 32, lch * 16);

#pragma unroll
    for (int p = 0; p < 4; p++) {
        int r = lr + p * 32;
        CP16(sb + lsw[p],         A  + (size_t)(m0 + r) * TD + lch * 8);
        CP16(sb + 16384 + lsw[p], Bt + (size_t)(n0 + r) * TD + lch * 8);
    }
    CP_COMMIT();

    for (int i = 0; i < 12; i++) {
        uint32_t stg = (uint32_t)(i & 1) * 32768;
        if (i < 11) {
            uint32_t nst = (uint32_t)((i + 1) & 1) * 32768;
#pragma unroll
            for (int p = 0; p < 4; p++) {
                int r = lr + p * 32;
                CP16(sb + nst + lsw[p],         A  + (size_t)(m0 + r) * TD + (i + 1) * 64 + lch * 8);
                CP16(sb + nst + 16384 + lsw[p], Bt + (size_t)(n0 + r) * TD + (i + 1) * 64 + lch * 8);
            }
            CP_COMMIT();
            CP_WAIT1();
        } else {
            CP_WAIT0();
        }
        __syncthreads();
#pragma unroll
        for (int ks = 0; ks < 4; ks++) {
            uint32_t af[4][4], bfr[4][2];
#pragma unroll
            for (int mf = 0; mf < 4; mf++)
                ldsm4(af[mf][0], af[mf][1], af[mf][2], af[mf][3],
                      sb + stg + row128(arow + mf * 16, ks * 32 + acolx));
#pragma unroll
            for (int j = 0; j < 4; j += 2)
                ldsm4(bfr[j][0], bfr[j][1], bfr[j + 1][0], bfr[j + 1][1],
                      sb + stg + 16384 + row128(brow0 + j * 8, ks * 32 + bcolx));
#pragma unroll
            for (int mf = 0; mf < 4; mf++)
#pragma unroll
                for (int nf = 0; nf < 4; nf++)
                    mma16816(c[mf][nf], af[mf], bfr[nf]);
        }
        __syncthreads();
    }
}

// ---------------- QKV GEMM (Q scaled by log2e; V written transposed) --------
#define GEMM_SMEM 65536
__global__ __launch_bounds__(256) void qkv_kernel() {
    extern __shared__ char smem[];
    int z = blockIdx.z;
    int m0 = blockIdx.x * 128, n0 = blockIdx.y * 128;
    float c[4][4][4] = {};
    gemm128(g_h, g_wt[z], smem, c, m0, n0);

    int tid = threadIdx.x, warp = tid >> 5, lane = tid & 31;
    int wm = (warp >> 2) * 64, wn = (warp & 3) * 32;

    if (z < 2) {
        bf16* G = (z == 0) ? g_q : g_k;
        float sc = (z == 0) ? LOG2E : 1.0f;
#pragma unroll
        for (int mf = 0; mf < 4; mf++) {
            int row = m0 + wm + mf * 16 + (lane >> 2);
            int batch = row >> 11, seq = row & (NSEQ - 1);
#pragma unroll
            for (int nf = 0; nf < 4; nf++) {
                int col = n0 + wn + nf * 8 + 2 * (lane & 3);
                int head = col >> 6, d = col & 63;
                bf16* D = G + ((size_t)(batch * NHEADS + head) * NSEQ + seq) * HDIM + d;
                *(uint32_t*)D = pk2(c[mf][nf][0] * sc, c[mf][nf][1] * sc);
                *(uint32_t*)(D + 8 * HDIM) = pk2(c[mf][nf][2] * sc, c[mf][nf][3] * sc);
            }
        }
    } else {
        bf16* ts = (bf16*)smem;     // [128 cols n][136 pitch m]
        __syncthreads();
#pragma unroll
        for (int mf = 0; mf < 4; mf++) {
            int lr0 = wm + mf * 16 + (lane >> 2);
#pragma unroll
            for (int nf = 0; nf < 4; nf++) {
                int lc = wn + nf * 8 + 2 * (lane & 3);
                uint32_t lo = pk2(c[mf][nf][0], c[mf][nf][2]);
                uint32_t hi = pk2(c[mf][nf][1], c[mf][nf][3]);
                ts[(size_t)lc * 136 + lr0]           = __ushort_as_bfloat16((unsigned short)(lo & 0xffff));
                ts[(size_t)lc * 136 + lr0 + 8]       = __ushort_as_bfloat16((unsigned short)(lo >> 16));
                ts[(size_t)(lc + 1) * 136 + lr0]     = __ushort_as_bfloat16((unsigned short)(hi & 0xffff));
                ts[(size_t)(lc + 1) * 136 + lr0 + 8] = __ushort_as_bfloat16((unsigned short)(hi >> 16));
            }
        }
        __syncthreads();
        int n = tid >> 1, mh = (tid & 1) * 64;
        int col = n0 + n, head = col >> 6, d = col & 63;
        int batch = blockIdx.x >> 4;
        int seq0 = (m0 & (NSEQ - 1)) + mh;
        bf16* D = g_vt + ((size_t)(batch * NHEADS + head) * HDIM + d) * NSEQ + seq0;
#pragma unroll
        for (int s = 0; s < 8; s++)
            *(uint4*)(D + s * 8) = *(uint4*)&ts[(size_t)n * 136 + mh + s * 8];
    }
}

// ---------------- Attention: 128 q/CTA, 4 warps x 32 q rows (R11 version) ---
// smem: Q 16K @0 | K 2x8K @16384 | V^T 2x8K @32768  (48KB static)
__global__ __launch_bounds__(128, 2) void attn_kernel() {
    __shared__ char smem[49152];
    int tid = threadIdx.x, warp = tid >> 5, lane = tid & 31;
    int q0 = blockIdx.x * 128, bh = blockIdx.y;

    const bf16* Qg = g_q + (size_t)bh * NSEQ * HDIM;
    const bf16* Kg = g_k + (size_t)bh * NSEQ * HDIM;
    const bf16* Vt = g_vt + (size_t)bh * HDIM * NSEQ;
    uint32_t sb = smem_u32(smem);

#pragma unroll
    for (int p = 0; p < 8; p++) {
        int idx = tid + p * 128;
        int r = idx >> 3, ch = idx & 7;
        CP16(sb + row128(r, ch * 16), Qg + (size_t)(q0 + r) * HDIM + ch * 8);
    }
    CP_COMMIT();

#pragma unroll
    for (int p = 0; p < 4; p++) {
        int idx = tid + p * 128;
        int r = idx >> 3, ch = idx & 7;
        uint32_t sw = row128(r, ch * 16);
        CP16(sb + 16384 + sw, Kg + (size_t)r * HDIM + ch * 8);
        CP16(sb + 32768 + sw, Vt + (size_t)r * NSEQ + ch * 8);
    }
    CP_COMMIT();

    CP_WAIT1();
    __syncthreads();

    uint32_t qf[2][4][4];
    int arow = warp * 32 + (lane & 15);
    int acolx = (lane & 16) ? 16 : 0;
#pragma unroll
    for (int mf = 0; mf < 2; mf++)
#pragma unroll
        for (int ks = 0; ks < 4; ks++)
            ldsm4(qf[mf][ks][0], qf[mf][ks][1], qf[mf][ks][2], qf[mf][ks][3],
                  sb + row128(arow + mf * 16, ks * 32 + acolx));

    float of[2][8][4] = {};
    float lsum[2][2] = {};
    int brow0 = ((lane & 16) ? 8 : 0) + (lane & 7);
    int bcolx = (lane & 8) ? 16 : 0;

    for (int kt = 0; kt < NSEQ / 64; kt++) {
        uint32_t stg = (uint32_t)(kt & 1) * 8192;
        if (kt < NSEQ / 64 - 1) {
            uint32_t nst = (uint32_t)((kt + 1) & 1) * 8192;
#pragma unroll
            for (int p = 0; p < 4; p++) {
                int idx = tid + p * 128;
                int r = idx >> 3, ch = idx & 7;
                uint32_t sw = row128(r, ch * 16);
                CP16(sb + 16384 + nst + sw, Kg + (size_t)((kt + 1) * 64 + r) * HDIM + ch * 8);
                CP16(sb + 32768 + nst + sw, Vt + (size_t)r * NSEQ + (kt + 1) * 64 + ch * 8);
            }
            CP_COMMIT();
            CP_WAIT1();
        } else {
            CP_WAIT0();
        }
        __syncthreads();

        // S' = (log2e*Q) @ K^T in two 32-kv halves; P = exp2(S')
        uint32_t pf[2][4][4];
#pragma unroll
        for (int half = 0; half < 2; half++) {
            float sf[2][4][4] = {};
#pragma unroll
            for (int ks = 0; ks < 4; ks++) {
                uint32_t bfr[4][2];
#pragma unroll
                for (int j = 0; j < 4; j += 2)
                    ldsm4(bfr[j][0], bfr[j][1], bfr[j + 1][0], bfr[j + 1][1],
                          sb + 16384 + stg + row128(brow0 + half * 32 + j * 8, ks * 32 + bcolx));
#pragma unroll
                for (int mf = 0; mf < 2; mf++)
#pragma unroll
                    for (int nf = 0; nf < 4; nf++)
                        mma16816(sf[mf][nf], qf[mf][ks], bfr[nf]);
            }
#pragma unroll
            for (int mf = 0; mf < 2; mf++)
#pragma unroll
                for (int j = 0; j < 2; j++) {
                    float e00 = ex2(sf[mf][2 * j][0]),     e01 = ex2(sf[mf][2 * j][1]);
                    float e02 = ex2(sf[mf][2 * j][2]),     e03 = ex2(sf[mf][2 * j][3]);
                    float e10 = ex2(sf[mf][2 * j + 1][0]), e11 = ex2(sf[mf][2 * j + 1][1]);
                    float e12 = ex2(sf[mf][2 * j + 1][2]), e13 = ex2(sf[mf][2 * j + 1][3]);
                    int pj = half * 2 + j;
                    pf[mf][pj][0] = pk2(e00, e01);
                    pf[mf][pj][1] = pk2(e02, e03);
                    pf[mf][pj][2] = pk2(e10, e11);
                    pf[mf][pj][3] = pk2(e12, e13);
                    lsum[mf][0] += e00 + e01 + e10 + e11;
                    lsum[mf][1] += e02 + e03 + e12 + e13;
                }
        }

        // O += P @ V : B from V^T [d][kv]
#pragma unroll
        for (int ks = 0; ks < 4; ks++) {
            uint32_t bfr[8][2];
#pragma unroll
            for (int j = 0; j < 8; j += 2)
                ldsm4(bfr[j][0], bfr[j][1], bfr[j + 1][0], bfr[j + 1][1],
                      sb + 32768 + stg + row128(brow0 + j * 8, ks * 32 + bcolx));
#pragma unroll
            for (int mf = 0; mf < 2; mf++)
#pragma unroll
                for (int nf = 0; nf < 8; nf++)
                    mma16816(of[mf][nf], pf[mf][ks], bfr[nf]);
        }
        __syncthreads();
    }

    float scale[2][2];
#pragma unroll
    for (int mf = 0; mf < 2; mf++)
#pragma unroll
        for (int h = 0; h < 2; h++) {
            float l = lsum[mf][h];
            l += __shfl_xor_sync(~0u, l, 1);
            l += __shfl_xor_sync(~0u, l, 2);
            scale[mf][h] = ATT_SCALE / l;
        }
    int batch = bh / NHEADS, head = bh % NHEADS;
#pragma unroll
    for (int mf = 0; mf < 2; mf++) {
        int r0 = q0 + warp * 32 + mf * 16 + (lane >> 2);
#pragma unroll
        for (int nf = 0; nf < 8; nf++) {
            int d = nf * 8 + 2 * (lane & 3);
            bf16* D = g_vals + ((size_t)(batch * NSEQ + r0)) * TD + head * HDIM + d;
            *(uint32_t*)D = pk2(of[mf][nf][0] * scale[mf][0], of[mf][nf][1] * scale[mf][0]);
            *(uint32_t*)(D + (size_t)8 * TD) =
                pk2(of[mf][nf][2] * scale[mf][1], of[mf][nf][3] * scale[mf][1]);
        }
    }
}

// ---------------- Output projection: out = vals @ Wo + bo + x ----------------
__global__ __launch_bounds__(256) void out_kernel(const float* __restrict__ bo,
                                                  const float* __restrict__ x,
                                                  float* __restrict__ out) {
    extern __shared__ char smem[];
    int m0 = blockIdx.x * 128, n0 = blockIdx.y * 128;
    float c[4][4][4] = {};
    gemm128(g_vals, g_wt[3], smem, c, m0, n0);

    int tid = threadIdx.x, warp = tid >> 5, lane = tid & 31;
    int wm = (warp >> 2) * 64, wn = (warp & 3) * 32;
#pragma unroll
    for (int mf = 0; mf < 4; mf++) {
        int row = m0 + wm + mf * 16 + (lane >> 2);
#pragma unroll
        for (int nf = 0; nf < 4; nf++) {
            int col = n0 + wn + nf * 8 + 2 * (lane & 3);
            float2 bv = *(const float2*)(bo + col);
            size_t off0 = (size_t)row * TD + col;
            size_t off1 = (size_t)(row + 8) * TD + col;
            float2 x0 = *(const float2*)(x + off0);
            float2 x1 = *(const float2*)(x + off1);
            *(float2*)(out + off0) = make_float2(c[mf][nf][0] + bv.x + x0.x,
                                                 c[mf][nf][1] + bv.y + x0.y);
            *(float2*)(out + off1) = make_float2(c[mf][nf][2] + bv.x + x1.x,
                                                 c[mf][nf][3] + bv.y + x1.y);
        }
    }
}

// ---------------------------------------------------------------------------
extern "C" void kernel_launch(void* const* d_in, const int* in_sizes, int n_in,
                              void* d_out, int out_size) {
    (void)in_sizes; (void)n_in; (void)out_size;
    const float* x     = (const float*)d_in[0];
    const float* Wq    = (const float*)d_in[1];
    const float* Wk    = (const float*)d_in[2];
    const float* Wv    = (const float*)d_in[3];
    const float* Wo    = (const float*)d_in[4];
    const float* bo    = (const float*)d_in[5];
    const float* gamma = (const float*)d_in[6];
    const float* beta  = (const float*)d_in[7];
    float* out = (float*)d_out;

    cudaFuncSetAttribute(qkv_kernel, cudaFuncAttributeMaxDynamicSharedMemorySize, GEMM_SMEM);
    cudaFuncSetAttribute(out_kernel, cudaFuncAttributeMaxDynamicSharedMemorySize, GEMM_SMEM);

    prep_kernel<<<NROWS + 4 * 24 * 24, 256>>>(x, gamma, beta, Wq, Wk, Wv, Wo);
    qkv_kernel<<<dim3(NROWS / 128, TD / 128, 3), 256, GEMM_SMEM>>>();
    attn_kernel<<<dim3(NSEQ / 128, NBH), 128>>>();
    out_kernel<<<dim3(NROWS / 128, TD / 128), 256, GEMM_SMEM>>>(bo, x, out);
}

// round 16
// speedup vs baseline: 1.1078x; 1.0308x over previous
#include <cuda_runtime.h>
#include <cuda_bf16.h>
#include <cstdint>

#define TD 768
#define NHEADS 12
#define HDIM 64
#define NSEQ 2048
#define NROWS 4096
#define NBH 24
#define ATT_SCALE 0.125f
#define LN_EPS 1e-5f
#define LOG2E 1.4426950408889634f

typedef __nv_bfloat16 bf16;

__device__ bf16 g_h[(size_t)NROWS * TD];
__device__ bf16 g_wt[4][(size_t)TD * TD];            // W^T [n][k]
__device__ bf16 g_q[(size_t)NBH * NSEQ * HDIM];      // pre-scaled by log2(e)
__device__ bf16 g_k[(size_t)NBH * NSEQ * HDIM];
__device__ bf16 g_vt[(size_t)NBH * HDIM * NSEQ];     // V^T [bh][d][seq]
__device__ bf16 g_vals[(size_t)NROWS * TD];

// ---------------- helpers ----------------
__device__ __forceinline__ uint32_t smem_u32(const void* p) {
    uint32_t a;
    asm("{ .reg .u64 t; cvta.to.shared.u64 t, %1; cvt.u32.u64 %0, t; }" : "=r"(a) : "l"(p));
    return a;
}
__device__ __forceinline__ uint32_t row128(int r, int cb) {
    uint32_t o = (uint32_t)(r * 128 + cb);
    return o ^ ((o >> 3) & 0x70);
}
__device__ __forceinline__ uint32_t pk2(float a, float b) {
    uint32_t r;
    asm("cvt.rn.satfinite.bf16x2.f32 %0, %1, %2;" : "=r"(r) : "f"(b), "f"(a));
    return r;
}
__device__ __forceinline__ float ex2(float x) {
    float r;
    asm("ex2.approx.ftz.f32 %0, %1;" : "=f"(r) : "f"(x));
    return r;
}
__device__ __forceinline__ void ldsm4(uint32_t& r0, uint32_t& r1, uint32_t& r2, uint32_t& r3,
                                      uint32_t addr) {
    asm volatile("ldmatrix.sync.aligned.m8n8.x4.shared.b16 {%0,%1,%2,%3}, [%4];"
        : "=r"(r0), "=r"(r1), "=r"(r2), "=r"(r3) : "r"(addr));
}
__device__ __forceinline__ void mma16816(float* c, const uint32_t* a, const uint32_t* b) {
    asm volatile("mma.sync.aligned.m16n8k16.row.col.f32.bf16.bf16.f32 "
        "{%0,%1,%2,%3}, {%4,%5,%6,%7}, {%8,%9}, {%0,%1,%2,%3};"
        : "+f"(c[0]), "+f"(c[1]), "+f"(c[2]), "+f"(c[3])
        : "r"(a[0]), "r"(a[1]), "r"(a[2]), "r"(a[3]), "r"(b[0]), "r"(b[1]));
}
#define CP16(dst, src) asm volatile("cp.async.cg.shared.global [%0], [%1], 16;" :: "r"(dst), "l"(src))
#define CP_COMMIT()    asm volatile("cp.async.commit_group;")
#define CP_WAIT0()     asm volatile("cp.async.wait_group 0;")
#define CP_WAIT1()     asm volatile("cp.async.wait_group 1;")

// ---------------- Fused prep: LN (blocks 0..4095) + W transpose (rest) ------
__global__ __launch_bounds__(256) void prep_kernel(const float* __restrict__ x,
                                                   const float* __restrict__ gamma,
                                                   const float* __restrict__ beta,
                                                   const float* __restrict__ Wq,
                                                   const float* __restrict__ Wk,
                                                   const float* __restrict__ Wv,
                                                   const float* __restrict__ Wo) {
    __shared__ float ss[8], sv[8];
    __shared__ float t[32][33];
    int bx = blockIdx.x;
    if (bx < NROWS) {
        int row = bx;
        const float* xr = x + (size_t)row * TD;
        float v[3], sum = 0.f, sq = 0.f;
#pragma unroll
        for (int p = 0; p < 3; p++) {
            v[p] = xr[threadIdx.x + p * 256];
            sum += v[p]; sq += v[p] * v[p];
        }
#pragma unroll
        for (int o = 16; o; o >>= 1) {
            sum += __shfl_xor_sync(~0u, sum, o);
            sq  += __shfl_xor_sync(~0u, sq, o);
        }
        int w = threadIdx.x >> 5, l = threadIdx.x & 31;
        if (l == 0) { ss[w] = sum; sv[w] = sq; }
        __syncthreads();
        if (w == 0) {
            sum = ss[l & 7]; sq = sv[l & 7];
#pragma unroll
            for (int o = 4; o; o >>= 1) {
                sum += __shfl_xor_sync(~0u, sum, o);
                sq  += __shfl_xor_sync(~0u, sq, o);
            }
            if (l == 0) { ss[0] = sum; sv[0] = sq; }
        }
        __syncthreads();
        float mean = ss[0] * (1.f / TD);
        float rstd = rsqrtf(sv[0] * (1.f / TD) - mean * mean + LN_EPS);
#pragma unroll
        for (int p = 0; p < 3; p++) {
            int i = threadIdx.x + p * 256;
            g_h[(size_t)row * TD + i] =
                __float2bfloat16_rn((v[p] - mean) * rstd * gamma[i] + beta[i]);
        }
    } else {
        int tile = bx - NROWS;
        int z = tile / 576;
        int rem = tile - z * 576;
        int n0 = (rem % 24) * 32, k0 = (rem / 24) * 32;
        const float* W = (z == 0) ? Wq : (z == 1) ? Wk : (z == 2) ? Wv : Wo;
        int tx = threadIdx.x & 31, ty = threadIdx.x >> 5;
#pragma unroll
        for (int i = 0; i < 4; i++)
            t[ty + 8 * i][tx] = W[(size_t)(k0 + ty + 8 * i) * TD + n0 + tx];
        __syncthreads();
#pragma unroll
        for (int i = 0; i < 4; i++)
            g_wt[z][(size_t)(n0 + ty + 8 * i) * TD + k0 + tx] =
                __float2bfloat16_rn(t[tx][ty + 8 * i]);
    }
}

// ---------------- core 128x128 GEMM mainloop (2-stage cp.async) -------------
__device__ __forceinline__ void gemm128(const bf16* __restrict__ A, const bf16* __restrict__ Bt,
                                        char* smem, float c[4][4][4], int m0, int n0) {
    int tid = threadIdx.x, warp = tid >> 5, lane = tid & 31;
    int wm = (warp >> 2) * 64, wn = (warp & 3) * 32;
    uint32_t sb = smem_u32(smem);
    int arow = wm + (lane & 15);
    int acolx = (lane & 16) ? 16 : 0;
    int brow0 = wn + ((lane & 16) ? 8 : 0) + (lane & 7);
    int bcolx = (lane & 8) ? 16 : 0;

    int lr = tid >> 3, lch = tid & 7;
    uint32_t lsw[4];
#pragma unroll
    for (int p = 0; p < 4; p++) lsw[p] = row128(lr + p * 32, lch * 16);

#pragma unroll
    for (int p = 0; p < 4; p++) {
        int r = lr + p * 32;
        CP16(sb + lsw[p],         A  + (size_t)(m0 + r) * TD + lch * 8);
        CP16(sb + 16384 + lsw[p], Bt + (size_t)(n0 + r) * TD + lch * 8);
    }
    CP_COMMIT();

    for (int i = 0; i < 12; i++) {
        uint32_t stg = (uint32_t)(i & 1) * 32768;
        if (i < 11) {
            uint32_t nst = (uint32_t)((i + 1) & 1) * 32768;
#pragma unroll
            for (int p = 0; p < 4; p++) {
                int r = lr + p * 32;
                CP16(sb + nst + lsw[p],         A  + (size_t)(m0 + r) * TD + (i + 1) * 64 + lch * 8);
                CP16(sb + nst + 16384 + lsw[p], Bt + (size_t)(n0 + r) * TD + (i + 1) * 64 + lch * 8);
            }
            CP_COMMIT();
            CP_WAIT1();
        } else {
            CP_WAIT0();
        }
        __syncthreads();
#pragma unroll
        for (int ks = 0; ks < 4; ks++) {
            uint32_t af[4][4], bfr[4][2];
#pragma unroll
            for (int mf = 0; mf < 4; mf++)
                ldsm4(af[mf][0], af[mf][1], af[mf][2], af[mf][3],
                      sb + stg + row128(arow + mf * 16, ks * 32 + acolx));
#pragma unroll
            for (int j = 0; j < 4; j += 2)
                ldsm4(bfr[j][0], bfr[j][1], bfr[j + 1][0], bfr[j + 1][1],
                      sb + stg + 16384 + row128(brow0 + j * 8, ks * 32 + bcolx));
#pragma unroll
            for (int mf = 0; mf < 4; mf++)
#pragma unroll
                for (int nf = 0; nf < 4; nf++)
                    mma16816(c[mf][nf], af[mf], bfr[nf]);
        }
        __syncthreads();
    }
}

// ---------------- QKV GEMM (Q scaled by log2e; V written transposed) --------
#define GEMM_SMEM 65536
__global__ __launch_bounds__(256) void qkv_kernel() {
    extern __shared__ char smem[];
    int z = blockIdx.z;
    int m0 = blockIdx.x * 128, n0 = blockIdx.y * 128;
    float c[4][4][4] = {};
    gemm128(g_h, g_wt[z], smem, c, m0, n0);

    int tid = threadIdx.x, warp = tid >> 5, lane = tid & 31;
    int wm = (warp >> 2) * 64, wn = (warp & 3) * 32;

    if (z < 2) {
        bf16* G = (z == 0) ? g_q : g_k;
        float sc = (z == 0) ? LOG2E : 1.0f;
#pragma unroll
        for (int mf = 0; mf < 4; mf++) {
            int row = m0 + wm + mf * 16 + (lane >> 2);
            int batch = row >> 11, seq = row & (NSEQ - 1);
#pragma unroll
            for (int nf = 0; nf < 4; nf++) {
                int col = n0 + wn + nf * 8 + 2 * (lane & 3);
                int head = col >> 6, d = col & 63;
                bf16* D = G + ((size_t)(batch * NHEADS + head) * NSEQ + seq) * HDIM + d;
                *(uint32_t*)D = pk2(c[mf][nf][0] * sc, c[mf][nf][1] * sc);
                *(uint32_t*)(D + 8 * HDIM) = pk2(c[mf][nf][2] * sc, c[mf][nf][3] * sc);
            }
        }
    } else {
        bf16* ts = (bf16*)smem;     // [128 cols n][136 pitch m]
        __syncthreads();
#pragma unroll
        for (int mf = 0; mf < 4; mf++) {
            int lr0 = wm + mf * 16 + (lane >> 2);
#pragma unroll
            for (int nf = 0; nf < 4; nf++) {
                int lc = wn + nf * 8 + 2 * (lane & 3);
                uint32_t lo = pk2(c[mf][nf][0], c[mf][nf][2]);
                uint32_t hi = pk2(c[mf][nf][1], c[mf][nf][3]);
                ts[(size_t)lc * 136 + lr0]           = __ushort_as_bfloat16((unsigned short)(lo & 0xffff));
                ts[(size_t)lc * 136 + lr0 + 8]       = __ushort_as_bfloat16((unsigned short)(lo >> 16));
                ts[(size_t)(lc + 1) * 136 + lr0]     = __ushort_as_bfloat16((unsigned short)(hi & 0xffff));
                ts[(size_t)(lc + 1) * 136 + lr0 + 8] = __ushort_as_bfloat16((unsigned short)(hi >> 16));
            }
        }
        __syncthreads();
        int n = tid >> 1, mh = (tid & 1) * 64;
        int col = n0 + n, head = col >> 6, d = col & 63;
        int batch = blockIdx.x >> 4;
        int seq0 = (m0 & (NSEQ - 1)) + mh;
        bf16* D = g_vt + ((size_t)(batch * NHEADS + head) * HDIM + d) * NSEQ + seq0;
#pragma unroll
        for (int s = 0; s < 8; s++)
            *(uint4*)(D + s * 8) = *(uint4*)&ts[(size_t)n * 136 + mh + s * 8];
    }
}

// ---------------- Attention: 128 q/CTA, 4 warps x 32 q rows (R11 version) ---
__global__ __launch_bounds__(128, 2) void attn_kernel() {
    __shared__ char smem[49152];
    int tid = threadIdx.x, warp = tid >> 5, lane = tid & 31;
    int q0 = blockIdx.x * 128, bh = blockIdx.y;

    const bf16* Qg = g_q + (size_t)bh * NSEQ * HDIM;
    const bf16* Kg = g_k + (size_t)bh * NSEQ * HDIM;
    const bf16* Vt = g_vt + (size_t)bh * HDIM * NSEQ;
    uint32_t sb = smem_u32(smem);

#pragma unroll
    for (int p = 0; p < 8; p++) {
        int idx = tid + p * 128;
        int r = idx >> 3, ch = idx & 7;
        CP16(sb + row128(r, ch * 16), Qg + (size_t)(q0 + r) * HDIM + ch * 8);
    }
    CP_COMMIT();

#pragma unroll
    for (int p = 0; p < 4; p++) {
        int idx = tid + p * 128;
        int r = idx >> 3, ch = idx & 7;
        uint32_t sw = row128(r, ch * 16);
        CP16(sb + 16384 + sw, Kg + (size_t)r * HDIM + ch * 8);
        CP16(sb + 32768 + sw, Vt + (size_t)r * NSEQ + ch * 8);
    }
    CP_COMMIT();

    CP_WAIT1();
    __syncthreads();

    uint32_t qf[2][4][4];
    int arow = warp * 32 + (lane & 15);
    int acolx = (lane & 16) ? 16 : 0;
#pragma unroll
    for (int mf = 0; mf < 2; mf++)
#pragma unroll
        for (int ks = 0; ks < 4; ks++)
            ldsm4(qf[mf][ks][0], qf[mf][ks][1], qf[mf][ks][2], qf[mf][ks][3],
                  sb + row128(arow + mf * 16, ks * 32 + acolx));

    float of[2][8][4] = {};
    float lsum[2][2] = {};
    int brow0 = ((lane & 16) ? 8 : 0) + (lane & 7);
    int bcolx = (lane & 8) ? 16 : 0;

    for (int kt = 0; kt < NSEQ / 64; kt++) {
        uint32_t stg = (uint32_t)(kt & 1) * 8192;
        if (kt < NSEQ / 64 - 1) {
            uint32_t nst = (uint32_t)((kt + 1) & 1) * 8192;
#pragma unroll
            for (int p = 0; p < 4; p++) {
                int idx = tid + p * 128;
                int r = idx >> 3, ch = idx & 7;
                uint32_t sw = row128(r, ch * 16);
                CP16(sb + 16384 + nst + sw, Kg + (size_t)((kt + 1) * 64 + r) * HDIM + ch * 8);
                CP16(sb + 32768 + nst + sw, Vt + (size_t)r * NSEQ + (kt + 1) * 64 + ch * 8);
            }
            CP_COMMIT();
            CP_WAIT1();
        } else {
            CP_WAIT0();
        }
        __syncthreads();

        uint32_t pf[2][4][4];
#pragma unroll
        for (int half = 0; half < 2; half++) {
            float sf[2][4][4] = {};
#pragma unroll
            for (int ks = 0; ks < 4; ks++) {
                uint32_t bfr[4][2];
#pragma unroll
                for (int j = 0; j < 4; j += 2)
                    ldsm4(bfr[j][0], bfr[j][1], bfr[j + 1][0], bfr[j + 1][1],
                          sb + 16384 + stg + row128(brow0 + half * 32 + j * 8, ks * 32 + bcolx));
#pragma unroll
                for (int mf = 0; mf < 2; mf++)
#pragma unroll
                    for (int nf = 0; nf < 4; nf++)
                        mma16816(sf[mf][nf], qf[mf][ks], bfr[nf]);
            }
#pragma unroll
            for (int mf = 0; mf < 2; mf++)
#pragma unroll
                for (int j = 0; j < 2; j++) {
                    float e00 = ex2(sf[mf][2 * j][0]),     e01 = ex2(sf[mf][2 * j][1]);
                    float e02 = ex2(sf[mf][2 * j][2]),     e03 = ex2(sf[mf][2 * j][3]);
                    float e10 = ex2(sf[mf][2 * j + 1][0]), e11 = ex2(sf[mf][2 * j + 1][1]);
                    float e12 = ex2(sf[mf][2 * j + 1][2]), e13 = ex2(sf[mf][2 * j + 1][3]);
                    int pj = half * 2 + j;
                    pf[mf][pj][0] = pk2(e00, e01);
                    pf[mf][pj][1] = pk2(e02, e03);
                    pf[mf][pj][2] = pk2(e10, e11);
                    pf[mf][pj][3] = pk2(e12, e13);
                    lsum[mf][0] += e00 + e01 + e10 + e11;
                    lsum[mf][1] += e02 + e03 + e12 + e13;
                }
        }

#pragma unroll
        for (int ks = 0; ks < 4; ks++) {
            uint32_t bfr[8][2];
#pragma unroll
            for (int j = 0; j < 8; j += 2)
                ldsm4(bfr[j][0], bfr[j][1], bfr[j + 1][0], bfr[j + 1][1],
                      sb + 32768 + stg + row128(brow0 + j * 8, ks * 32 + bcolx));
#pragma unroll
            for (int mf = 0; mf < 2; mf++)
#pragma unroll
                for (int nf = 0; nf < 8; nf++)
                    mma16816(of[mf][nf], pf[mf][ks], bfr[nf]);
        }
        __syncthreads();
    }

    float scale[2][2];
#pragma unroll
    for (int mf = 0; mf < 2; mf++)
#pragma unroll
        for (int h = 0; h < 2; h++) {
            float l = lsum[mf][h];
            l += __shfl_xor_sync(~0u, l, 1);
            l += __shfl_xor_sync(~0u, l, 2);
            scale[mf][h] = ATT_SCALE / l;
        }
    int batch = bh / NHEADS, head = bh % NHEADS;
#pragma unroll
    for (int mf = 0; mf < 2; mf++) {
        int r0 = q0 + warp * 32 + mf * 16 + (lane >> 2);
#pragma unroll
        for (int nf = 0; nf < 8; nf++) {
            int d = nf * 8 + 2 * (lane & 3);
            bf16* D = g_vals + ((size_t)(batch * NSEQ + r0)) * TD + head * HDIM + d;
            *(uint32_t*)D = pk2(of[mf][nf][0] * scale[mf][0], of[mf][nf][1] * scale[mf][0]);
            *(uint32_t*)(D + (size_t)8 * TD) =
                pk2(of[mf][nf][2] * scale[mf][1], of[mf][nf][3] * scale[mf][1]);
        }
    }
}

// ---------------- Output projection: 64x128 tiles, 3 CTA/SM -----------------
// smem: stage s at s*24576 { A 8K, B 16K }; 48KB total. 8 warps, 32x32 each.
#define OUT_SMEM 49152
__global__ __launch_bounds__(256, 3) void out_kernel(const float* __restrict__ bo,
                                                     const float* __restrict__ x,
                                                     float* __restrict__ out) {
    extern __shared__ char smem[];
    int m0 = blockIdx.x * 64, n0 = blockIdx.y * 128;
    int tid = threadIdx.x, warp = tid >> 5, lane = tid & 31;
    int wm = (warp >> 2) * 32, wn = (warp & 3) * 32;
    uint32_t sb = smem_u32(smem);
    int arow = wm + (lane & 15);
    int acolx = (lane & 16) ? 16 : 0;
    int brow0 = wn + ((lane & 16) ? 8 : 0) + (lane & 7);
    int bcolx = (lane & 8) ? 16 : 0;

    // loaders: A 64x64 (2 uint4/thread), B 128x64 (4 uint4/thread)
    int lr = tid >> 3, lch = tid & 7;
    uint32_t lswA[2], lswB[4];
#pragma unroll
    for (int p = 0; p < 2; p++) lswA[p] = row128(lr + p * 32, lch * 16);
#pragma unroll
    for (int p = 0; p < 4; p++) lswB[p] = row128(lr + p * 32, lch * 16);

    const bf16* A = g_vals;
    const bf16* Bt = g_wt[3];

#pragma unroll
    for (int p = 0; p < 2; p++)
        CP16(sb + lswA[p], A + (size_t)(m0 + lr + p * 32) * TD + lch * 8);
#pragma unroll
    for (int p = 0; p < 4; p++)
        CP16(sb + 8192 + lswB[p], Bt + (size_t)(n0 + lr + p * 32) * TD + lch * 8);
    CP_COMMIT();

    float c[2][4][4] = {};
    for (int i = 0; i < 12; i++) {
        uint32_t stg = (uint32_t)(i & 1) * 24576;
        if (i < 11) {
            uint32_t nst = (uint32_t)((i + 1) & 1) * 24576;
#pragma unroll
            for (int p = 0; p < 2; p++)
                CP16(sb + nst + lswA[p], A + (size_t)(m0 + lr + p * 32) * TD + (i + 1) * 64 + lch * 8);
#pragma unroll
            for (int p = 0; p < 4; p++)
                CP16(sb + nst + 8192 + lswB[p], Bt + (size_t)(n0 + lr + p * 32) * TD + (i + 1) * 64 + lch * 8);
            CP_COMMIT();
            CP_WAIT1();
        } else {
            CP_WAIT0();
        }
        __syncthreads();
#pragma unroll
        for (int ks = 0; ks < 4; ks++) {
            uint32_t af[2][4], bfr[4][2];
#pragma unroll
            for (int mf = 0; mf < 2; mf++)
                ldsm4(af[mf][0], af[mf][1], af[mf][2], af[mf][3],
                      sb + stg + row128(arow + mf * 16, ks * 32 + acolx));
#pragma unroll
            for (int j = 0; j < 4; j += 2)
                ldsm4(bfr[j][0], bfr[j][1], bfr[j + 1][0], bfr[j + 1][1],
                      sb + stg + 8192 + row128(brow0 + j * 8, ks * 32 + bcolx));
#pragma unroll
            for (int mf = 0; mf < 2; mf++)
#pragma unroll
                for (int nf = 0; nf < 4; nf++)
                    mma16816(c[mf][nf], af[mf], bfr[nf]);
        }
        __syncthreads();
    }

    // epilogue: + bias + residual
#pragma unroll
    for (int mf = 0; mf < 2; mf++) {
        int row = m0 + wm + mf * 16 + (lane >> 2);
#pragma unroll
        for (int nf = 0; nf < 4; nf++) {
            int col = n0 + wn + nf * 8 + 2 * (lane & 3);
            float2 bv = *(const float2*)(bo + col);
            size_t off0 = (size_t)row * TD + col;
            size_t off1 = (size_t)(row + 8) * TD + col;
            float2 x0 = *(const float2*)(x + off0);
            float2 x1 = *(const float2*)(x + off1);
            *(float2*)(out + off0) = make_float2(c[mf][nf][0] + bv.x + x0.x,
                                                 c[mf][nf][1] + bv.y + x0.y);
            *(float2*)(out + off1) = make_float2(c[mf][nf][2] + bv.x + x1.x,
                                                 c[mf][nf][3] + bv.y + x1.y);
        }
    }
}

// ---------------------------------------------------------------------------
extern "C" void kernel_launch(void* const* d_in, const int* in_sizes, int n_in,
                              void* d_out, int out_size) {
    (void)in_sizes; (void)n_in; (void)out_size;
    const float* x     = (const float*)d_in[0];
    const float* Wq    = (const float*)d_in[1];
    const float* Wk    = (const float*)d_in[2];
    const float* Wv    = (const float*)d_in[3];
    const float* Wo    = (const float*)d_in[4];
    const float* bo    = (const float*)d_in[5];
    const float* gamma = (const float*)d_in[6];
    const float* beta  = (const float*)d_in[7];
    float* out = (float*)d_out;

    cudaFuncSetAttribute(qkv_kernel, cudaFuncAttributeMaxDynamicSharedMemorySize, GEMM_SMEM);
    cudaFuncSetAttribute(out_kernel, cudaFuncAttributeMaxDynamicSharedMemorySize, OUT_SMEM);

    prep_kernel<<<NROWS + 4 * 24 * 24, 256>>>(x, gamma, beta, Wq, Wk, Wv, Wo);
    qkv_kernel<<<dim3(NROWS / 128, TD / 128, 3), 256, GEMM_SMEM>>>();
    attn_kernel<<<dim3(NSEQ / 128, NBH), 128>>>();
    out_kernel<<<dim3(NROWS / 64, TD / 128), 256, OUT_SMEM>>>(bo, x, out);
}